// round 6
// baseline (speedup 1.0000x reference)
#include <cuda_runtime.h>
#include <math.h>

#define N_REG 576
#define IMG   2048
#define H     1024
#define MID   512
#define VOCAB 32000

// ---------------- scratch (device globals; no allocation allowed) -----------
__device__ float g_x1[4096];            // [h2 | vbar | we]
__device__ float g_x2[3072];            // [v | h1n]
__device__ float g_gates[4096];         // reused lstm1 then lstm2
__device__ float g_h1t[MID];
__device__ float g_vt[4][N_REG * MID];  // K-split partials (deterministic)
__device__ float g_logits[N_REG];

// ---------------- K1: vbar + embedding gather + x1 build --------------------
__global__ void k_build_x1(const float* __restrict__ V,
                           const float* __restrict__ h2,
                           const float* __restrict__ emb,
                           const int*   __restrict__ w) {
    int j = blockIdx.x * 256 + threadIdx.x;       // 4096 threads
    if (j < 1024) {
        g_x1[j] = h2[j];
    } else if (j < 1024 + IMG) {
        int c = j - 1024;
        float s = 0.f;
        #pragma unroll 8
        for (int r = 0; r < N_REG; r++) s += V[(long)r * IMG + c];
        g_x1[j] = s * (1.0f / N_REG);
    } else {
        g_x1[j] = emb[(long)w[0] * 1024 + (j - 3072)];
    }
}

// ---------------- K2: fused [vt GEMM blocks 0..143] + [lstm1 gates 144..655] -
// vt:   [576 x 2048] @ [2048 x 512]^T -> 4 K-split partials. 64(reg)x128(mid)
//       tiles, 256 threads, 4x8 micro-tile (1.5 B LDS / FMA -> compute-bound).
// gates: warp-per-row matvec, rows 0..4095 of W_ih1 (L=4096) + W_hh1.
#define VT_BLOCKS 144
__global__ void __launch_bounds__(256) k_main1(
        const float* __restrict__ V,     const float* __restrict__ lv_w,
        const float* __restrict__ W_ih,  const float* __restrict__ W_hh,
        const float* __restrict__ b_ih,  const float* __restrict__ b_hh,
        const float* __restrict__ h) {
    __shared__ float smem[5248];    // gates: sx[4096]+sh[1024]; vt: As[16*68]+Bs[16*132]
    int tid = threadIdx.x;

    if (blockIdx.x < VT_BLOCKS) {
        // ---------------- vt GEMM path ----------------
        float* As = smem;             // [16][68]  (k, reg)
        float* Bs = smem + 16 * 68;   // [16][132] (k, mid)
        int b2  = blockIdx.x;
        int kz  = b2 / 36;
        int rem = b2 % 36;
        int m0  = (rem & 3) * 128;
        int r0  = (rem >> 2) * 64;
        int kbase = kz * 512;

        int lr  = tid >> 2;            // 0..63  A row
        int ka4 = (tid & 3) * 4;       // A k-group
        int lm  = tid >> 1;            // 0..127 B row
        int kb8 = (tid & 1) * 8;       // B k-group
        int ty  = tid >> 4;            // 0..15 -> regs ty*4..+3
        int tx  = tid & 15;            // 0..15 -> mids tx*8..+7

        float acc[4][8] = {};
        for (int kk = 0; kk < 512; kk += 16) {
            float4 av  = *(const float4*)(V    + (long)(r0 + lr) * IMG + kbase + kk + ka4);
            float4 bv0 = *(const float4*)(lv_w + (long)(m0 + lm) * IMG + kbase + kk + kb8);
            float4 bv1 = *(const float4*)(lv_w + (long)(m0 + lm) * IMG + kbase + kk + kb8 + 4);
            __syncthreads();
            As[(ka4 + 0) * 68 + lr] = av.x; As[(ka4 + 1) * 68 + lr] = av.y;
            As[(ka4 + 2) * 68 + lr] = av.z; As[(ka4 + 3) * 68 + lr] = av.w;
            Bs[(kb8 + 0) * 132 + lm] = bv0.x; Bs[(kb8 + 1) * 132 + lm] = bv0.y;
            Bs[(kb8 + 2) * 132 + lm] = bv0.z; Bs[(kb8 + 3) * 132 + lm] = bv0.w;
            Bs[(kb8 + 4) * 132 + lm] = bv1.x; Bs[(kb8 + 5) * 132 + lm] = bv1.y;
            Bs[(kb8 + 6) * 132 + lm] = bv1.z; Bs[(kb8 + 7) * 132 + lm] = bv1.w;
            __syncthreads();
            #pragma unroll
            for (int k = 0; k < 16; k++) {
                float4 a4 = *(const float4*)&As[k * 68 + ty * 4];
                float4 b0 = *(const float4*)&Bs[k * 132 + tx * 8];
                float4 b1 = *(const float4*)&Bs[k * 132 + tx * 8 + 4];
                float a[4] = {a4.x, a4.y, a4.z, a4.w};
                float b[8] = {b0.x, b0.y, b0.z, b0.w, b1.x, b1.y, b1.z, b1.w};
                #pragma unroll
                for (int i = 0; i < 4; i++)
                    #pragma unroll
                    for (int j = 0; j < 8; j++) acc[i][j] += a[i] * b[j];
            }
        }
        float* outp = g_vt[kz];
        #pragma unroll
        for (int i = 0; i < 4; i++) {
            long base = (long)(r0 + ty * 4 + i) * MID + m0 + tx * 8;
            *(float4*)(outp + base)     = make_float4(acc[i][0], acc[i][1], acc[i][2], acc[i][3]);
            *(float4*)(outp + base + 4) = make_float4(acc[i][4], acc[i][5], acc[i][6], acc[i][7]);
        }
    } else {
        // ---------------- lstm1 gates path ----------------
        float* sx = smem;            // 4096
        float* sh = smem + 4096;     // 1024
        for (int i = tid; i < 4096; i += 256) sx[i] = g_x1[i];
        for (int i = tid; i < 1024; i += 256) sh[i] = h[i];
        __syncthreads();

        int warp = tid >> 5, lane = tid & 31;
        int j = (blockIdx.x - VT_BLOCKS) * 8 + warp;

        const float4* wr = (const float4*)(W_ih + (long)j * 4096);
        const float4* xr = (const float4*)sx;
        float acc = 0.f;
        #pragma unroll 4
        for (int i = lane; i < 1024; i += 32) {
            float4 v = wr[i];
            float4 xv = xr[i];
            acc += v.x * xv.x + v.y * xv.y + v.z * xv.z + v.w * xv.w;
        }
        const float4* wh = (const float4*)(W_hh + (long)j * 1024);
        const float4* hr = (const float4*)sh;
        #pragma unroll 4
        for (int i = lane; i < 256; i += 32) {
            float4 v = wh[i];
            float4 hv = hr[i];
            acc += v.x * hv.x + v.y * hv.y + v.z * hv.z + v.w * hv.w;
        }
        #pragma unroll
        for (int o = 16; o > 0; o >>= 1) acc += __shfl_xor_sync(0xffffffffu, acc, o);
        if (lane == 0) g_gates[j] = acc + b_ih[j] + b_hh[j];
    }
}

// ---------------- K3: fused lstm1 cell (redundant per block) + h1t ----------
__global__ void k_cell1_h1t(const float* __restrict__ c1,
                            const float* __restrict__ lh_w,
                            const float* __restrict__ lh_b,
                            float* __restrict__ h1n_out,
                            float* __restrict__ c1n_out) {
    __shared__ float sh[1024];       // h1n
    int tid = threadIdx.x;
    #pragma unroll
    for (int q = 0; q < 4; q++) {
        int j = tid + q * 256;
        float gi = g_gates[j], gf = g_gates[1024 + j];
        float gg = g_gates[2048 + j], go = g_gates[3072 + j];
        float i = 1.f / (1.f + expf(-gi));
        float f = 1.f / (1.f + expf(-gf));
        float o = 1.f / (1.f + expf(-go));
        float c = f * c1[j] + i * tanhf(gg);
        float hh = o * tanhf(c);
        sh[j] = hh;
        if (blockIdx.x == 0) { h1n_out[j] = hh; c1n_out[j] = c; }
    }
    __syncthreads();

    int warp = tid >> 5, lane = tid & 31;
    int m = blockIdx.x * 8 + warp;                // 64 blocks -> 512 rows
    const float4* wr = (const float4*)(lh_w + (long)m * 1024);
    const float4* hr = (const float4*)sh;
    float acc = 0.f;
    #pragma unroll 4
    for (int i = lane; i < 256; i += 32) {
        float4 v = wr[i];
        float4 hv = hr[i];
        acc += v.x * hv.x + v.y * hv.y + v.z * hv.z + v.w * hv.w;
    }
    #pragma unroll
    for (int o = 16; o > 0; o >>= 1) acc += __shfl_xor_sync(0xffffffffu, acc, o);
    if (lane == 0) g_h1t[m] = acc + lh_b[m];
}

// ---------------- K4: attention logits: one block per region ----------------
__global__ void k_logits(const float* __restrict__ lv_b,
                         const float* __restrict__ att_w,
                         const float* __restrict__ att_b) {
    int n = blockIdx.x;
    int tid = threadIdx.x;                         // 128
    const float* __restrict__ p0 = g_vt[0];
    const float* __restrict__ p1 = g_vt[1];
    const float* __restrict__ p2 = g_vt[2];
    const float* __restrict__ p3 = g_vt[3];
    float acc = 0.f;
    for (int m = tid; m < MID; m += 128) {
        int idx = n * MID + m;
        float v = p0[idx] + p1[idx] + p2[idx] + p3[idx] + lv_b[m] + g_h1t[m];
        acc += tanhf(v) * att_w[m];
    }
    __shared__ float red[4];
    #pragma unroll
    for (int o = 16; o > 0; o >>= 1) acc += __shfl_xor_sync(0xffffffffu, acc, o);
    if ((tid & 31) == 0) red[tid >> 5] = acc;
    __syncthreads();
    if (tid == 0) g_logits[n] = red[0] + red[1] + red[2] + red[3] + att_b[0];
}

// ---------------- K5: fused softmax (redundant per block) + x2 build --------
// Every block computes the IDENTICAL softmax over 576 logits (deterministic,
// bitwise-equal across blocks), then handles its slice of x2.
__global__ void k_smax_x2(const float* __restrict__ V,
                          const float* __restrict__ h1n) {
    __shared__ float sa[N_REG];
    __shared__ float red[8];
    __shared__ float s_max, s_inv;
    int tid = threadIdx.x;                         // 256

    for (int n = tid; n < N_REG; n += 256) sa[n] = g_logits[n];
    __syncthreads();

    float m = -1e30f;
    for (int n = tid; n < N_REG; n += 256) m = fmaxf(m, sa[n]);
    #pragma unroll
    for (int o = 16; o > 0; o >>= 1) m = fmaxf(m, __shfl_xor_sync(0xffffffffu, m, o));
    if ((tid & 31) == 0) red[tid >> 5] = m;
    __syncthreads();
    if (tid == 0) {
        float mm = red[0];
        for (int i = 1; i < 8; i++) mm = fmaxf(mm, red[i]);
        s_max = mm;
    }
    __syncthreads();
    float s = 0.f;
    for (int n = tid; n < N_REG; n += 256) {
        float e = expf(sa[n] - s_max);
        sa[n] = e;
        s += e;
    }
    #pragma unroll
    for (int o = 16; o > 0; o >>= 1) s += __shfl_xor_sync(0xffffffffu, s, o);
    if ((tid & 31) == 0) red[tid >> 5] = s;
    __syncthreads();
    if (tid == 0) {
        float ss = 0.f;
        for (int i = 0; i < 8; i++) ss += red[i];
        s_inv = 1.f / ss;
    }
    __syncthreads();
    for (int n = tid; n < N_REG; n += 256) sa[n] *= s_inv;
    __syncthreads();

    int k = blockIdx.x * 256 + tid;                // 12 blocks -> 3072
    if (k < IMG) {
        float acc = 0.f;
        #pragma unroll 8
        for (int n = 0; n < N_REG; n++) acc += sa[n] * V[(long)n * IMG + k];
        g_x2[k] = acc;
    } else {
        g_x2[k] = h1n[k - IMG];
    }
}

// ---------------- K6: lstm2 gates matvec (warp per row) ---------------------
__global__ void k_gates2(const float* __restrict__ W_ih,
                         const float* __restrict__ W_hh,
                         const float* __restrict__ b_ih,
                         const float* __restrict__ b_hh,
                         const float* __restrict__ h) {
    __shared__ float sx[3072];
    __shared__ float sh[1024];
    int tid = threadIdx.x;
    for (int i = tid; i < 3072; i += 256) sx[i] = g_x2[i];
    for (int i = tid; i < 1024; i += 256) sh[i] = h[i];
    __syncthreads();

    int warp = tid >> 5, lane = tid & 31;
    int j = blockIdx.x * 8 + warp;

    const float4* wr = (const float4*)(W_ih + (long)j * 3072);
    const float4* xr = (const float4*)sx;
    float acc = 0.f;
    #pragma unroll 4
    for (int i = lane; i < 768; i += 32) {
        float4 v = wr[i];
        float4 xv = xr[i];
        acc += v.x * xv.x + v.y * xv.y + v.z * xv.z + v.w * xv.w;
    }
    const float4* wh = (const float4*)(W_hh + (long)j * 1024);
    const float4* hr = (const float4*)sh;
    #pragma unroll 4
    for (int i = lane; i < 256; i += 32) {
        float4 v = wh[i];
        float4 hv = hr[i];
        acc += v.x * hv.x + v.y * hv.y + v.z * hv.z + v.w * hv.w;
    }
    #pragma unroll
    for (int o = 16; o > 0; o >>= 1) acc += __shfl_xor_sync(0xffffffffu, acc, o);
    if (lane == 0) g_gates[j] = acc + b_ih[j] + b_hh[j];
}

// ---------------- K7: lstm2 cell elementwise --------------------------------
__global__ void k_cell(const float* __restrict__ c_in,
                       float* __restrict__ h_out,
                       float* __restrict__ c_out) {
    int j = blockIdx.x * 256 + threadIdx.x;       // 1024 threads
    float gi = g_gates[j], gf = g_gates[1024 + j], gg = g_gates[2048 + j], go = g_gates[3072 + j];
    float i = 1.f / (1.f + expf(-gi));
    float f = 1.f / (1.f + expf(-gf));
    float o = 1.f / (1.f + expf(-go));
    float c = f * c_in[j] + i * tanhf(gg);
    c_out[j] = c;
    h_out[j] = o * tanhf(c);
}

// ---------------- K8: vocab projection: warp per row ------------------------
__global__ void k_out(const float* __restrict__ lin_w,
                      const float* __restrict__ lin_b,
                      const float* __restrict__ h2n,
                      float* __restrict__ o) {
    __shared__ float sh[1024];
    int tid = threadIdx.x;
    for (int i = tid; i < 1024; i += 256) sh[i] = h2n[i];
    __syncthreads();
    int warp = tid >> 5, lane = tid & 31;
    int j = blockIdx.x * 8 + warp;                 // 4000 blocks
    const float4* wr = (const float4*)(lin_w + (long)j * 1024);
    const float4* hr = (const float4*)sh;
    float acc = 0.f;
    #pragma unroll 4
    for (int i = lane; i < 256; i += 32) {
        float4 v = wr[i];
        float4 hv = hr[i];
        acc += v.x * hv.x + v.y * hv.y + v.z * hv.z + v.w * hv.w;
    }
    #pragma unroll
    for (int o2 = 16; o2 > 0; o2 >>= 1) acc += __shfl_xor_sync(0xffffffffu, acc, o2);
    if (lane == 0) o[j] = acc + lin_b[j];
}

// ---------------- launch ----------------------------------------------------
extern "C" void kernel_launch(void* const* d_in, const int* in_sizes, int n_in,
                              void* d_out, int out_size) {
    const float* V     = (const float*)d_in[0];
    const int*   w     = (const int*)  d_in[1];
    const float* h1    = (const float*)d_in[2];
    const float* c1    = (const float*)d_in[3];
    const float* h2    = (const float*)d_in[4];
    const float* c2    = (const float*)d_in[5];
    const float* emb   = (const float*)d_in[6];
    const float* W_ih1 = (const float*)d_in[7];
    const float* W_hh1 = (const float*)d_in[8];
    const float* b_ih1 = (const float*)d_in[9];
    const float* b_hh1 = (const float*)d_in[10];
    const float* W_ih2 = (const float*)d_in[11];
    const float* W_hh2 = (const float*)d_in[12];
    const float* b_ih2 = (const float*)d_in[13];
    const float* b_hh2 = (const float*)d_in[14];
    const float* lv_w  = (const float*)d_in[15];
    const float* lv_b  = (const float*)d_in[16];
    const float* lh_w  = (const float*)d_in[17];
    const float* lh_b  = (const float*)d_in[18];
    const float* att_w = (const float*)d_in[19];
    const float* att_b = (const float*)d_in[20];
    const float* lin_w = (const float*)d_in[21];
    const float* lin_b = (const float*)d_in[22];

    float* out = (float*)d_out;
    float* o_p   = out;
    float* h1n_p = out + VOCAB;
    float* c1n_p = out + VOCAB + 1024;
    float* h2n_p = out + VOCAB + 2048;
    float* c2n_p = out + VOCAB + 3072;

    // K1: x1 = [h2 | mean(V) | emb[w]]
    k_build_x1<<<16, 256>>>(V, h2, emb, w);
    // K2: fused vt GEMM (blocks 0..143, scheduled first) + lstm1 gates (144..655)
    k_main1<<<VT_BLOCKS + 512, 256>>>(V, lv_w, W_ih1, W_hh1, b_ih1, b_hh1, h1);
    // K3: lstm1 cell + h1t
    k_cell1_h1t<<<64, 256>>>(c1, lh_w, lh_b, h1n_p, c1n_p);
    // K4: attention logits
    k_logits<<<N_REG, 128>>>(lv_b, att_w, att_b);
    // K5: softmax + weighted pooling + x2 build
    k_smax_x2<<<12, 256>>>(V, h1n_p);
    // K6: lstm2 gates
    k_gates2<<<512, 256>>>(W_ih2, W_hh2, b_ih2, b_hh2, h2);
    // K7: lstm2 cell
    k_cell<<<4, 256>>>(c2, h2n_p, c2n_p);
    // K8: vocab projection
    k_out<<<VOCAB / 8, 256>>>(lin_w, lin_b, h2n_p, o_p);
}